// round 4
// baseline (speedup 1.0000x reference)
#include <cuda_runtime.h>
#include <math.h>

// Problem constants (fixed by the dataset)
#define HEADS   8
#define OUT_F   64
#define HO      512          // HEADS * OUT_F
#define IN_F    256
#define MAXN    50048        // padded node count (multiple of 128)
#define MAXE    1600000

// ---------------- scratch (static __device__ globals, no runtime alloc) -----
__device__ __align__(16) static float g_t[(size_t)MAXN * HO];   // 102.5 MB  t[n][h*64+o]
__device__ __align__(16) static float g_w[(size_t)MAXN * HEADS];// exp(Ar)   w[n][h]
__device__ static int g_cnt[MAXN];
__device__ static int g_rowptr[MAXN + 1];
__device__ static int g_cur[MAXN];
__device__ static int g_col[MAXE];
__device__ static int g_part[128];

// ---------------- CSR build -------------------------------------------------
__global__ void k_zero(int n) {
    int i = blockIdx.x * blockDim.x + threadIdx.x;
    if (i < n) g_cnt[i] = 0;
}

__global__ void k_hist(const int* __restrict__ src, int E) {
    int i = blockIdx.x * blockDim.x + threadIdx.x;
    if (i < E) atomicAdd(&g_cnt[src[i]], 1);
}

__global__ void k_scan1(int N) {
    __shared__ int s[1024];
    int tid = threadIdx.x;
    int i = blockIdx.x * 1024 + tid;
    int v = (i < N) ? g_cnt[i] : 0;
    s[tid] = v;
    __syncthreads();
    #pragma unroll
    for (int off = 1; off < 1024; off <<= 1) {
        int add = (tid >= off) ? s[tid - off] : 0;
        __syncthreads();
        s[tid] += add;
        __syncthreads();
    }
    if (i < N) g_rowptr[i + 1] = s[tid];
    if (tid == 1023) g_part[blockIdx.x] = s[1023];
}

__global__ void k_scan2(int B) {
    int run = 0;
    for (int b = 0; b < B; ++b) { int t = g_part[b]; g_part[b] = run; run += t; }
}

__global__ void k_scan3(int N) {
    int i = blockIdx.x * 1024 + threadIdx.x;
    if (i < N) {
        int rp = g_rowptr[i + 1] + g_part[blockIdx.x];
        g_rowptr[i + 1] = rp;
        if (i + 1 < N) g_cur[i + 1] = rp;
    }
    if (i == 0) { g_rowptr[0] = 0; g_cur[0] = 0; }
}

__global__ void k_scatter(const int* __restrict__ src, const int* __restrict__ dst, int E) {
    int i = blockIdx.x * blockDim.x + threadIdx.x;
    if (i < E) {
        int p = atomicAdd(&g_cur[src[i]], 1);
        g_col[p] = dst[i];
    }
}

// ---------------- GEMM: t = x (M x 256)  ·  Ws^T (256 x 512) ---------------
// Register-tiled fp32 SGEMM: BM=BN=128, BK=16, 256 threads, 8x8 per thread.
__global__ __launch_bounds__(256) void k_gemm(const float* __restrict__ A,
                                              const float* __restrict__ B,
                                              int M) {
    __shared__ float As[16][132];  // [k][m], padded
    __shared__ float Bs[16][132];  // [k][n]

    int tid = threadIdx.x;
    int tx = tid & 15;       // 0..15  -> n
    int ty = tid >> 4;       // 0..15  -> m
    int m0 = blockIdx.x * 128;
    int n0 = blockIdx.y * 128;

    float acc[8][8];
    #pragma unroll
    for (int i = 0; i < 8; ++i)
        #pragma unroll
        for (int j = 0; j < 8; ++j) acc[i][j] = 0.f;

    for (int k0 = 0; k0 < IN_F; k0 += 16) {
        // cooperative loads: A tile 128x16 (512 float4, 2/thread), B tile same
        #pragma unroll
        for (int r = 0; r < 2; ++r) {
            int id  = tid + r * 256;
            int row = id >> 2;
            int c4  = (id & 3) * 4;
            float4 va = make_float4(0.f, 0.f, 0.f, 0.f);
            if (m0 + row < M)
                va = *(const float4*)&A[(size_t)(m0 + row) * IN_F + k0 + c4];
            As[c4 + 0][row] = va.x; As[c4 + 1][row] = va.y;
            As[c4 + 2][row] = va.z; As[c4 + 3][row] = va.w;
            float4 vb = *(const float4*)&B[(size_t)(n0 + row) * IN_F + k0 + c4];
            Bs[c4 + 0][row] = vb.x; Bs[c4 + 1][row] = vb.y;
            Bs[c4 + 2][row] = vb.z; Bs[c4 + 3][row] = vb.w;
        }
        __syncthreads();

        #pragma unroll
        for (int kk = 0; kk < 16; ++kk) {
            float4 a0 = *(const float4*)&As[kk][ty * 8];
            float4 a1 = *(const float4*)&As[kk][ty * 8 + 4];
            float4 b0 = *(const float4*)&Bs[kk][tx * 8];
            float4 b1 = *(const float4*)&Bs[kk][tx * 8 + 4];
            float a[8] = {a0.x, a0.y, a0.z, a0.w, a1.x, a1.y, a1.z, a1.w};
            float b[8] = {b0.x, b0.y, b0.z, b0.w, b1.x, b1.y, b1.z, b1.w};
            #pragma unroll
            for (int i = 0; i < 8; ++i)
                #pragma unroll
                for (int j = 0; j < 8; ++j)
                    acc[i][j] = fmaf(a[i], b[j], acc[i][j]);
        }
        __syncthreads();
    }

    #pragma unroll
    for (int i = 0; i < 8; ++i) {
        int m = m0 + ty * 8 + i;
        if (m < M) {
            float* cp = &g_t[(size_t)m * HO + n0 + tx * 8];
            *(float4*)cp       = make_float4(acc[i][0], acc[i][1], acc[i][2], acc[i][3]);
            *(float4*)(cp + 4) = make_float4(acc[i][4], acc[i][5], acc[i][6], acc[i][7]);
        }
    }
}

// ---------------- w[n][h] = exp( t[n,h,:] . a_r[h,:] ) ----------------------
// As layout: [8][128][1]; a_r[h][o] = As[h*128 + 64 + o]
__global__ __launch_bounds__(256) void k_wexp(const float* __restrict__ As_in, int N) {
    int n    = blockIdx.x;
    int tid  = threadIdx.x;
    int h    = tid >> 5;
    int lane = tid & 31;
    const float* tr = g_t + (size_t)n * HO + h * OUT_F;
    const float* ar = As_in + h * 128 + OUT_F;
    float s = tr[lane] * ar[lane] + tr[lane + 32] * ar[lane + 32];
    #pragma unroll
    for (int off = 16; off > 0; off >>= 1)
        s += __shfl_xor_sync(0xffffffffu, s, off);
    if (lane == 0) g_w[(size_t)n * HEADS + h] = expf(s);
}

// ---------------- aggregation + ELU -----------------------------------------
// One block (128 thr) per node. Thread j owns out[n, 4j..4j+3]; head h = j/16.
// alpha_e = w[dst_e,h] / W[n,h]  (Al cancels; max-shift cancels in the ratio).
__global__ __launch_bounds__(128) void k_agg(float* __restrict__ out) {
    __shared__ float s_invW[8];
    __shared__ int   s_col[128];

    int n   = blockIdx.x;
    int tid = threadIdx.x;
    int rs  = g_rowptr[n];
    int re  = g_rowptr[n + 1];
    int h   = tid >> 4;

    if (re == rs) {  // no outgoing edges: out = elu(0) = 0
        *(float4*)&out[(size_t)n * HO + tid * 4] = make_float4(0.f, 0.f, 0.f, 0.f);
        return;
    }

    // phase 1: warp 0 computes W[n,h] = sum_e w[dst_e, h]
    if (tid < 32) {
        float4 p0 = make_float4(0.f, 0.f, 0.f, 0.f);
        float4 p1 = make_float4(0.f, 0.f, 0.f, 0.f);
        for (int i = rs + tid; i < re; i += 32) {
            int d = g_col[i];
            const float4* wp = (const float4*)&g_w[(size_t)d * 8];
            float4 w0 = wp[0], w1 = wp[1];
            p0.x += w0.x; p0.y += w0.y; p0.z += w0.z; p0.w += w0.w;
            p1.x += w1.x; p1.y += w1.y; p1.z += w1.z; p1.w += w1.w;
        }
        #pragma unroll
        for (int off = 16; off > 0; off >>= 1) {
            p0.x += __shfl_xor_sync(0xffffffffu, p0.x, off);
            p0.y += __shfl_xor_sync(0xffffffffu, p0.y, off);
            p0.z += __shfl_xor_sync(0xffffffffu, p0.z, off);
            p0.w += __shfl_xor_sync(0xffffffffu, p0.w, off);
            p1.x += __shfl_xor_sync(0xffffffffu, p1.x, off);
            p1.y += __shfl_xor_sync(0xffffffffu, p1.y, off);
            p1.z += __shfl_xor_sync(0xffffffffu, p1.z, off);
            p1.w += __shfl_xor_sync(0xffffffffu, p1.w, off);
        }
        if (tid == 0) {
            s_invW[0] = 1.f / p0.x; s_invW[1] = 1.f / p0.y;
            s_invW[2] = 1.f / p0.z; s_invW[3] = 1.f / p0.w;
            s_invW[4] = 1.f / p1.x; s_invW[5] = 1.f / p1.y;
            s_invW[6] = 1.f / p1.z; s_invW[7] = 1.f / p1.w;
        }
    }
    __syncthreads();

    float invW = s_invW[h];
    float4 acc = make_float4(0.f, 0.f, 0.f, 0.f);
    const float4* t4 = (const float4*)g_t;

    for (int base = rs; base < re; base += 128) {
        int nload = min(128, re - base);
        if (tid < nload) s_col[tid] = g_col[base + tid];
        __syncthreads();
        #pragma unroll 4
        for (int e = 0; e < nload; ++e) {
            int d = s_col[e];
            float coef = __ldg(&g_w[(size_t)d * 8 + h]) * invW;
            float4 tv = t4[(size_t)d * 128 + tid];   // coalesced 2KB row gather
            acc.x = fmaf(coef, tv.x, acc.x);
            acc.y = fmaf(coef, tv.y, acc.y);
            acc.z = fmaf(coef, tv.z, acc.z);
            acc.w = fmaf(coef, tv.w, acc.w);
        }
        __syncthreads();
    }

    float4 r;
    r.x = acc.x > 0.f ? acc.x : expm1f(acc.x);
    r.y = acc.y > 0.f ? acc.y : expm1f(acc.y);
    r.z = acc.z > 0.f ? acc.z : expm1f(acc.z);
    r.w = acc.w > 0.f ? acc.w : expm1f(acc.w);
    __stcs((float4*)&out[(size_t)n * HO + tid * 4], r);  // stream out, keep L2 for t
}

// ---------------- launch ----------------------------------------------------
extern "C" void kernel_launch(void* const* d_in, const int* in_sizes, int n_in,
                              void* d_out, int out_size) {
    const float* x   = (const float*)d_in[0];
    const int*   src = (const int*)  d_in[1];
    const int*   dst = (const int*)  d_in[2];
    const float* Ws  = (const float*)d_in[3];
    const float* As  = (const float*)d_in[4];
    float* out = (float*)d_out;

    int N = in_sizes[0] / IN_F;   // 50000
    int E = in_sizes[1];          // 1600000

    // CSR build (by src)
    k_zero<<<(N + 255) / 256, 256>>>(N);
    k_hist<<<(E + 255) / 256, 256>>>(src, E);
    int B = (N + 1023) / 1024;
    k_scan1<<<B, 1024>>>(N);
    k_scan2<<<1, 1>>>(B);
    k_scan3<<<B, 1024>>>(N);
    k_scatter<<<(E + 255) / 256, 256>>>(src, dst, E);

    // dense feature transform + attention weights
    dim3 gg((N + 127) / 128, HO / 128);
    k_gemm<<<gg, 256>>>(x, Ws, N);
    k_wexp<<<N, 256>>>(As, N);

    // softmax-weighted aggregation + ELU
    k_agg<<<N, 128>>>(out);
}

// round 6
// speedup vs baseline: 1.2492x; 1.2492x over previous
#include <cuda_runtime.h>
#include <cuda_bf16.h>
#include <math.h>
#include <stdint.h>

// Problem constants (fixed by the dataset)
#define HEADS   8
#define OUT_F   64
#define HO      512          // HEADS * OUT_F
#define IN_F    256
#define MAXN    50048        // padded node count (multiple of 128)
#define MAXE    1600000

// ---------------- scratch (static __device__ globals, no runtime alloc) -----
__device__ __align__(16) static float g_t[(size_t)MAXN * HO];   // 102.5 MB  t[n][h*64+o]
__device__ __align__(16) static float g_w[(size_t)MAXN * HEADS];// exp(Ar)   w[n][h]
__device__ static int g_cnt[MAXN];
__device__ static int g_rowptr[MAXN + 1];
__device__ static int g_cur[MAXN];
__device__ static int g_col[MAXE];
__device__ static int g_part[128];

// ---------------- CSR build -------------------------------------------------
__global__ void k_zero(int n) {
    int i = blockIdx.x * blockDim.x + threadIdx.x;
    if (i < n) g_cnt[i] = 0;
}

__global__ void k_hist(const int* __restrict__ src, int E) {
    int i = blockIdx.x * blockDim.x + threadIdx.x;
    if (i < E) atomicAdd(&g_cnt[src[i]], 1);
}

__global__ void k_scan1(int N) {
    __shared__ int s[1024];
    int tid = threadIdx.x;
    int i = blockIdx.x * 1024 + tid;
    int v = (i < N) ? g_cnt[i] : 0;
    s[tid] = v;
    __syncthreads();
    #pragma unroll
    for (int off = 1; off < 1024; off <<= 1) {
        int add = (tid >= off) ? s[tid - off] : 0;
        __syncthreads();
        s[tid] += add;
        __syncthreads();
    }
    if (i < N) g_rowptr[i + 1] = s[tid];
    if (tid == 1023) g_part[blockIdx.x] = s[1023];
}

__global__ void k_scan2(int B) {
    int run = 0;
    for (int b = 0; b < B; ++b) { int t = g_part[b]; g_part[b] = run; run += t; }
}

__global__ void k_scan3(int N) {
    int i = blockIdx.x * 1024 + threadIdx.x;
    if (i < N) {
        int rp = g_rowptr[i + 1] + g_part[blockIdx.x];
        g_rowptr[i + 1] = rp;
        if (i + 1 < N) g_cur[i + 1] = rp;
    }
    if (i == 0) { g_rowptr[0] = 0; g_cur[0] = 0; }
}

__global__ void k_scatter(const int* __restrict__ src, const int* __restrict__ dst, int E) {
    int i = blockIdx.x * blockDim.x + threadIdx.x;
    if (i < E) {
        int p = atomicAdd(&g_cur[src[i]], 1);
        g_col[p] = dst[i];
    }
}

// ---------------- tf32 MMA GEMM: t = x (M x 256) · Ws^T (256 x 512) --------
// BM=BN=128, BK=32. 256 threads = 8 warps in 2(m) x 4(n); warp tile 64x32.
// mma.sync.m16n8k8 tf32, fp32 accum. smem rows padded to 136 (136 mod 32 = 8
// => the four lane%4 column-groups land on disjoint bank octets: conflict-free).
#define SMP 136

__device__ __forceinline__ uint32_t f2tf32(float x) {
    uint32_t u;
    asm("cvt.rna.tf32.f32 %0, %1;" : "=r"(u) : "f"(x));
    return u;
}

__global__ __launch_bounds__(256) void k_gemm(const float* __restrict__ A,
                                              const float* __restrict__ B,
                                              int M) {
    __shared__ float As[32][SMP];   // [k][m], tf32 bit patterns
    __shared__ float Bs[32][SMP];   // [k][n]

    int tid   = threadIdx.x;
    int lane  = tid & 31;
    int warp  = tid >> 5;
    int wm    = (warp & 1) * 64;    // warp m-offset within tile
    int wn    = (warp >> 1) * 32;   // warp n-offset within tile
    int m0    = blockIdx.x * 128;
    int n0    = blockIdx.y * 128;

    float acc[4][4][4];
    #pragma unroll
    for (int mi = 0; mi < 4; ++mi)
        #pragma unroll
        for (int ni = 0; ni < 4; ++ni)
            #pragma unroll
            for (int j = 0; j < 4; ++j) acc[mi][ni][j] = 0.f;

    for (int k0 = 0; k0 < IN_F; k0 += 32) {
        // cooperative loads: 128x32 fp32 per tile = 1024 float4; 4/thread each
        #pragma unroll
        for (int r = 0; r < 4; ++r) {
            int id  = tid + r * 256;
            int row = id >> 3;              // 0..127
            int c4  = (id & 7) * 4;         // 0..28
            float4 va = make_float4(0.f, 0.f, 0.f, 0.f);
            if (m0 + row < M)
                va = *(const float4*)&A[(size_t)(m0 + row) * IN_F + k0 + c4];
            As[c4 + 0][row] = __uint_as_float(f2tf32(va.x));
            As[c4 + 1][row] = __uint_as_float(f2tf32(va.y));
            As[c4 + 2][row] = __uint_as_float(f2tf32(va.z));
            As[c4 + 3][row] = __uint_as_float(f2tf32(va.w));
            float4 vb = *(const float4*)&B[(size_t)(n0 + row) * IN_F + k0 + c4];
            Bs[c4 + 0][row] = __uint_as_float(f2tf32(vb.x));
            Bs[c4 + 1][row] = __uint_as_float(f2tf32(vb.y));
            Bs[c4 + 2][row] = __uint_as_float(f2tf32(vb.z));
            Bs[c4 + 3][row] = __uint_as_float(f2tf32(vb.w));
        }
        __syncthreads();

        int lr = lane >> 2;   // 0..7
        int lc = lane & 3;    // 0..3
        #pragma unroll
        for (int kk = 0; kk < 32; kk += 8) {
            uint32_t afr[4][4];
            uint32_t bfr[4][2];
            #pragma unroll
            for (int mi = 0; mi < 4; ++mi) {
                int rb = wm + mi * 16;
                afr[mi][0] = __float_as_uint(As[kk + lc    ][rb + lr    ]);
                afr[mi][1] = __float_as_uint(As[kk + lc    ][rb + lr + 8]);
                afr[mi][2] = __float_as_uint(As[kk + lc + 4][rb + lr    ]);
                afr[mi][3] = __float_as_uint(As[kk + lc + 4][rb + lr + 8]);
            }
            #pragma unroll
            for (int ni = 0; ni < 4; ++ni) {
                int nb = wn + ni * 8;
                bfr[ni][0] = __float_as_uint(Bs[kk + lc    ][nb + lr]);
                bfr[ni][1] = __float_as_uint(Bs[kk + lc + 4][nb + lr]);
            }
            #pragma unroll
            for (int mi = 0; mi < 4; ++mi)
                #pragma unroll
                for (int ni = 0; ni < 4; ++ni) {
                    asm volatile(
                        "mma.sync.aligned.m16n8k8.row.col.f32.tf32.tf32.f32 "
                        "{%0,%1,%2,%3}, {%4,%5,%6,%7}, {%8,%9}, {%0,%1,%2,%3};\n"
                        : "+f"(acc[mi][ni][0]), "+f"(acc[mi][ni][1]),
                          "+f"(acc[mi][ni][2]), "+f"(acc[mi][ni][3])
                        : "r"(afr[mi][0]), "r"(afr[mi][1]),
                          "r"(afr[mi][2]), "r"(afr[mi][3]),
                          "r"(bfr[ni][0]), "r"(bfr[ni][1]));
                }
        }
        __syncthreads();
    }

    // epilogue: write fp32 t
    int lr = lane >> 2;
    int lc = lane & 3;
    #pragma unroll
    for (int mi = 0; mi < 4; ++mi) {
        int r0 = m0 + wm + mi * 16 + lr;
        int r1 = r0 + 8;
        #pragma unroll
        for (int ni = 0; ni < 4; ++ni) {
            int c = n0 + wn + ni * 8 + lc * 2;
            if (r0 < M)
                *(float2*)&g_t[(size_t)r0 * HO + c] =
                    make_float2(acc[mi][ni][0], acc[mi][ni][1]);
            if (r1 < M)
                *(float2*)&g_t[(size_t)r1 * HO + c] =
                    make_float2(acc[mi][ni][2], acc[mi][ni][3]);
        }
    }
}

// ---------------- w[n][h] = exp( t[n,h,:] . a_r[h,:] ) ----------------------
// As layout: [8][128][1]; a_r[h][o] = As[h*128 + 64 + o]
__global__ __launch_bounds__(256) void k_wexp(const float* __restrict__ As_in, int N) {
    int n    = blockIdx.x;
    int tid  = threadIdx.x;
    int h    = tid >> 5;
    int lane = tid & 31;
    const float* tr = g_t + (size_t)n * HO + h * OUT_F;
    const float* ar = As_in + h * 128 + OUT_F;
    float s = tr[lane] * ar[lane] + tr[lane + 32] * ar[lane + 32];
    #pragma unroll
    for (int off = 16; off > 0; off >>= 1)
        s += __shfl_xor_sync(0xffffffffu, s, off);
    if (lane == 0) g_w[(size_t)n * HEADS + h] = expf(s);
}

// ---------------- aggregation + ELU (fp32 gather) ---------------------------
// One block (128 thr) per node. Thread j owns out[n, 4j..4j+3]; head h = j/16.
// alpha_e = w[dst_e,h] / W[n,h]  (Al cancels; max-shift cancels in the ratio).
__global__ __launch_bounds__(128) void k_agg(float* __restrict__ out) {
    __shared__ float s_invW[8];
    __shared__ int   s_col[128];

    int n   = blockIdx.x;
    int tid = threadIdx.x;
    int rs  = g_rowptr[n];
    int re  = g_rowptr[n + 1];
    int h   = tid >> 4;

    if (re == rs) {  // no outgoing edges: out = elu(0) = 0
        *(float4*)&out[(size_t)n * HO + tid * 4] = make_float4(0.f, 0.f, 0.f, 0.f);
        return;
    }

    // phase 1: warp 0 computes W[n,h] = sum_e w[dst_e, h]
    if (tid < 32) {
        float4 p0 = make_float4(0.f, 0.f, 0.f, 0.f);
        float4 p1 = make_float4(0.f, 0.f, 0.f, 0.f);
        for (int i = rs + tid; i < re; i += 32) {
            int d = g_col[i];
            const float4* wp = (const float4*)&g_w[(size_t)d * 8];
            float4 w0 = wp[0], w1 = wp[1];
            p0.x += w0.x; p0.y += w0.y; p0.z += w0.z; p0.w += w0.w;
            p1.x += w1.x; p1.y += w1.y; p1.z += w1.z; p1.w += w1.w;
        }
        #pragma unroll
        for (int off = 16; off > 0; off >>= 1) {
            p0.x += __shfl_xor_sync(0xffffffffu, p0.x, off);
            p0.y += __shfl_xor_sync(0xffffffffu, p0.y, off);
            p0.z += __shfl_xor_sync(0xffffffffu, p0.z, off);
            p0.w += __shfl_xor_sync(0xffffffffu, p0.w, off);
            p1.x += __shfl_xor_sync(0xffffffffu, p1.x, off);
            p1.y += __shfl_xor_sync(0xffffffffu, p1.y, off);
            p1.z += __shfl_xor_sync(0xffffffffu, p1.z, off);
            p1.w += __shfl_xor_sync(0xffffffffu, p1.w, off);
        }
        if (tid == 0) {
            s_invW[0] = 1.f / p0.x; s_invW[1] = 1.f / p0.y;
            s_invW[2] = 1.f / p0.z; s_invW[3] = 1.f / p0.w;
            s_invW[4] = 1.f / p1.x; s_invW[5] = 1.f / p1.y;
            s_invW[6] = 1.f / p1.z; s_invW[7] = 1.f / p1.w;
        }
    }
    __syncthreads();

    float invW = s_invW[h];
    float4 acc = make_float4(0.f, 0.f, 0.f, 0.f);
    const float4* t4 = (const float4*)g_t;

    for (int base = rs; base < re; base += 128) {
        int nload = min(128, re - base);
        if (tid < nload) s_col[tid] = g_col[base + tid];
        __syncthreads();
        #pragma unroll 4
        for (int e = 0; e < nload; ++e) {
            int d = s_col[e];
            float coef = __ldg(&g_w[(size_t)d * 8 + h]) * invW;
            float4 tv = t4[(size_t)d * 128 + tid];   // coalesced 2KB row gather
            acc.x = fmaf(coef, tv.x, acc.x);
            acc.y = fmaf(coef, tv.y, acc.y);
            acc.z = fmaf(coef, tv.z, acc.z);
            acc.w = fmaf(coef, tv.w, acc.w);
        }
        __syncthreads();
    }

    float4 r;
    r.x = acc.x > 0.f ? acc.x : expm1f(acc.x);
    r.y = acc.y > 0.f ? acc.y : expm1f(acc.y);
    r.z = acc.z > 0.f ? acc.z : expm1f(acc.z);
    r.w = acc.w > 0.f ? acc.w : expm1f(acc.w);
    __stcs((float4*)&out[(size_t)n * HO + tid * 4], r);  // stream out, keep L2 for t
}

// ---------------- launch ----------------------------------------------------
extern "C" void kernel_launch(void* const* d_in, const int* in_sizes, int n_in,
                              void* d_out, int out_size) {
    const float* x   = (const float*)d_in[0];
    const int*   src = (const int*)  d_in[1];
    const int*   dst = (const int*)  d_in[2];
    const float* Ws  = (const float*)d_in[3];
    const float* As  = (const float*)d_in[4];
    float* out = (float*)d_out;

    int N = in_sizes[0] / IN_F;   // 50000
    int E = in_sizes[1];          // 1600000

    // CSR build (by src)
    k_zero<<<(N + 255) / 256, 256>>>(N);
    k_hist<<<(E + 255) / 256, 256>>>(src, E);
    int B = (N + 1023) / 1024;
    k_scan1<<<B, 1024>>>(N);
    k_scan2<<<1, 1>>>(B);
    k_scan3<<<B, 1024>>>(N);
    k_scatter<<<(E + 255) / 256, 256>>>(src, dst, E);

    // dense feature transform + attention weights
    dim3 gg((N + 127) / 128, HO / 128);
    k_gemm<<<gg, 256>>>(x, Ws, N);
    k_wexp<<<N, 256>>>(As, N);

    // softmax-weighted aggregation + ELU
    k_agg<<<N, 128>>>(out);
}

// round 7
// speedup vs baseline: 1.5302x; 1.2250x over previous
#include <cuda_runtime.h>
#include <cuda_fp16.h>
#include <math.h>
#include <stdint.h>

// Problem constants (fixed by the dataset)
#define HEADS   8
#define OUT_F   64
#define HO      512          // HEADS * OUT_F
#define IN_F    256
#define MAXN    50048        // padded node count (multiple of 128)
#define MAXE    1600000

// ---------------- scratch (static __device__ globals, no runtime alloc) -----
__device__ __align__(16) static __half g_th[(size_t)MAXN * HO]; // 51.2 MB fp16 t (gather)
__device__ __align__(16) static float  g_w[(size_t)MAXN * HEADS]; // logits -> exp(Ar)
__device__ static int g_cnt[MAXN];
__device__ static int g_rowptr[MAXN + 1];
__device__ static int g_cur[MAXN];
__device__ static int g_col[MAXE];
__device__ static int g_part[128];

// ---------------- CSR build -------------------------------------------------
__global__ void k_zero(int n) {
    int i = blockIdx.x * blockDim.x + threadIdx.x;
    if (i < n) g_cnt[i] = 0;
}

__global__ void k_hist(const int* __restrict__ src, int E) {
    int i = blockIdx.x * blockDim.x + threadIdx.x;
    if (i < E) atomicAdd(&g_cnt[src[i]], 1);
}

__global__ void k_scan1(int N) {
    __shared__ int s[1024];
    int tid = threadIdx.x;
    int i = blockIdx.x * 1024 + tid;
    int v = (i < N) ? g_cnt[i] : 0;
    s[tid] = v;
    __syncthreads();
    #pragma unroll
    for (int off = 1; off < 1024; off <<= 1) {
        int add = (tid >= off) ? s[tid - off] : 0;
        __syncthreads();
        s[tid] += add;
        __syncthreads();
    }
    if (i < N) g_rowptr[i + 1] = s[tid];
    if (tid == 1023) g_part[blockIdx.x] = s[1023];
}

__global__ void k_scan2(int B) {
    int run = 0;
    for (int b = 0; b < B; ++b) { int t = g_part[b]; g_part[b] = run; run += t; }
}

__global__ void k_scan3(int N) {
    int i = blockIdx.x * 1024 + threadIdx.x;
    if (i < N) {
        int rp = g_rowptr[i + 1] + g_part[blockIdx.x];
        g_rowptr[i + 1] = rp;
        if (i + 1 < N) g_cur[i + 1] = rp;
    }
    if (i == 0) { g_rowptr[0] = 0; g_cur[0] = 0; }
}

__global__ void k_scatter(const int* __restrict__ src, const int* __restrict__ dst, int E) {
    int i = blockIdx.x * blockDim.x + threadIdx.x;
    if (i < E) {
        int p = atomicAdd(&g_cur[src[i]], 1);
        g_col[p] = dst[i];
    }
}

// ---------------- tf32 MMA GEMM: t = x (M x 256) · Ws^T (256 x 512) --------
// BM=BN=128, BK=32. 256 threads = 8 warps in 2(m) x 4(n); warp tile 64x32.
// Epilogue: writes fp16 t AND per-row logits t[m,h,:].a_r[h,:] for the 2
// complete heads covered by this block's 128-column slice (fp32 accumulators,
// block-local shared reduction, no global atomics).
#define SMP 136

__device__ __forceinline__ uint32_t f2tf32(float x) {
    uint32_t u;
    asm("cvt.rna.tf32.f32 %0, %1;" : "=r"(u) : "f"(x));
    return u;
}

__global__ __launch_bounds__(256) void k_gemm(const float* __restrict__ A,
                                              const float* __restrict__ B,
                                              const float* __restrict__ As_in,
                                              int M) {
    __shared__ float As[32][SMP];     // [k][m], tf32 bit patterns
    __shared__ float Bs[32][SMP];     // [k][n]
    __shared__ float s_ar[128];       // a_r for this block's 128 cols
    __shared__ float s_logit[128][2]; // per-row logits for the block's 2 heads

    int tid   = threadIdx.x;
    int lane  = tid & 31;
    int warp  = tid >> 5;
    int wm    = (warp & 1) * 64;    // warp m-offset within tile
    int wn    = (warp >> 1) * 32;   // warp n-offset within tile
    int m0    = blockIdx.x * 128;
    int n0    = blockIdx.y * 128;

    // a_r for global col c: As_in[(c/64)*128 + 64 + (c%64)]
    if (tid < 128) {
        int c = n0 + tid;
        s_ar[tid] = As_in[(c >> 6) * 128 + 64 + (c & 63)];
    }
    ((float*)s_logit)[tid] = 0.f;   // zero 256 floats = whole array

    float acc[4][4][4];
    #pragma unroll
    for (int mi = 0; mi < 4; ++mi)
        #pragma unroll
        for (int ni = 0; ni < 4; ++ni)
            #pragma unroll
            for (int j = 0; j < 4; ++j) acc[mi][ni][j] = 0.f;

    for (int k0 = 0; k0 < IN_F; k0 += 32) {
        // cooperative loads: 128x32 fp32 per tile = 1024 float4; 4/thread each
        #pragma unroll
        for (int r = 0; r < 4; ++r) {
            int id  = tid + r * 256;
            int row = id >> 3;              // 0..127
            int c4  = (id & 7) * 4;         // 0..28
            float4 va = make_float4(0.f, 0.f, 0.f, 0.f);
            if (m0 + row < M)
                va = *(const float4*)&A[(size_t)(m0 + row) * IN_F + k0 + c4];
            As[c4 + 0][row] = __uint_as_float(f2tf32(va.x));
            As[c4 + 1][row] = __uint_as_float(f2tf32(va.y));
            As[c4 + 2][row] = __uint_as_float(f2tf32(va.z));
            As[c4 + 3][row] = __uint_as_float(f2tf32(va.w));
            float4 vb = *(const float4*)&B[(size_t)(n0 + row) * IN_F + k0 + c4];
            Bs[c4 + 0][row] = __uint_as_float(f2tf32(vb.x));
            Bs[c4 + 1][row] = __uint_as_float(f2tf32(vb.y));
            Bs[c4 + 2][row] = __uint_as_float(f2tf32(vb.z));
            Bs[c4 + 3][row] = __uint_as_float(f2tf32(vb.w));
        }
        __syncthreads();

        int lr = lane >> 2;   // 0..7
        int lc = lane & 3;    // 0..3
        #pragma unroll
        for (int kk = 0; kk < 32; kk += 8) {
            uint32_t afr[4][4];
            uint32_t bfr[4][2];
            #pragma unroll
            for (int mi = 0; mi < 4; ++mi) {
                int rb = wm + mi * 16;
                afr[mi][0] = __float_as_uint(As[kk + lc    ][rb + lr    ]);
                afr[mi][1] = __float_as_uint(As[kk + lc    ][rb + lr + 8]);
                afr[mi][2] = __float_as_uint(As[kk + lc + 4][rb + lr    ]);
                afr[mi][3] = __float_as_uint(As[kk + lc + 4][rb + lr + 8]);
            }
            #pragma unroll
            for (int ni = 0; ni < 4; ++ni) {
                int nb = wn + ni * 8;
                bfr[ni][0] = __float_as_uint(Bs[kk + lc    ][nb + lr]);
                bfr[ni][1] = __float_as_uint(Bs[kk + lc + 4][nb + lr]);
            }
            #pragma unroll
            for (int mi = 0; mi < 4; ++mi)
                #pragma unroll
                for (int ni = 0; ni < 4; ++ni) {
                    asm volatile(
                        "mma.sync.aligned.m16n8k8.row.col.f32.tf32.tf32.f32 "
                        "{%0,%1,%2,%3}, {%4,%5,%6,%7}, {%8,%9}, {%0,%1,%2,%3};\n"
                        : "+f"(acc[mi][ni][0]), "+f"(acc[mi][ni][1]),
                          "+f"(acc[mi][ni][2]), "+f"(acc[mi][ni][3])
                        : "r"(afr[mi][0]), "r"(afr[mi][1]),
                          "r"(afr[mi][2]), "r"(afr[mi][3]),
                          "r"(bfr[ni][0]), "r"(bfr[ni][1]));
                }
        }
        __syncthreads();
    }

    // epilogue: fp16 t store + block-local logit reduction
    int lr = lane >> 2;
    int lc = lane & 3;
    int head_local = warp >> 2;   // warps 0-3 -> cols 0-63 (head 0); 4-7 -> head 1
    #pragma unroll
    for (int mi = 0; mi < 4; ++mi) {
        int r0 = m0 + wm + mi * 16 + lr;
        int r1 = r0 + 8;
        float p0 = 0.f, p1 = 0.f;
        #pragma unroll
        for (int ni = 0; ni < 4; ++ni) {
            int cl = wn + ni * 8 + lc * 2;    // block-local col
            int c  = n0 + cl;
            p0 = fmaf(acc[mi][ni][0], s_ar[cl], fmaf(acc[mi][ni][1], s_ar[cl + 1], p0));
            p1 = fmaf(acc[mi][ni][2], s_ar[cl], fmaf(acc[mi][ni][3], s_ar[cl + 1], p1));
            if (r0 < M)
                *(__half2*)&g_th[(size_t)r0 * HO + c] =
                    __floats2half2_rn(acc[mi][ni][0], acc[mi][ni][1]);
            if (r1 < M)
                *(__half2*)&g_th[(size_t)r1 * HO + c] =
                    __floats2half2_rn(acc[mi][ni][2], acc[mi][ni][3]);
        }
        atomicAdd(&s_logit[wm + mi * 16 + lr    ][head_local], p0);
        atomicAdd(&s_logit[wm + mi * 16 + lr + 8][head_local], p1);
    }
    __syncthreads();

    if (tid < 128 && m0 + tid < M) {
        int hb = blockIdx.y * 2;
        g_w[(size_t)(m0 + tid) * HEADS + hb    ] = s_logit[tid][0];
        g_w[(size_t)(m0 + tid) * HEADS + hb + 1] = s_logit[tid][1];
    }
}

// ---------------- in-place exp over logits ----------------------------------
__global__ void k_exps(int total) {
    int i = blockIdx.x * blockDim.x + threadIdx.x;
    if (i < total) g_w[i] = expf(g_w[i]);
}

// ---------------- aggregation + ELU (fp16 gather) ---------------------------
// One block (128 thr) per node. Thread j owns out[n, 4j..4j+3]; head h = j/16.
// alpha_e = w[dst_e,h] / W[n,h]  (Al cancels; max-shift cancels in the ratio).
__global__ __launch_bounds__(128) void k_agg(float* __restrict__ out) {
    __shared__ float s_invW[8];
    __shared__ int   s_col[128];

    int n   = blockIdx.x;
    int tid = threadIdx.x;
    int rs  = g_rowptr[n];
    int re  = g_rowptr[n + 1];
    int h   = tid >> 4;

    if (re == rs) {  // no outgoing edges: out = elu(0) = 0
        *(float4*)&out[(size_t)n * HO + tid * 4] = make_float4(0.f, 0.f, 0.f, 0.f);
        return;
    }

    // phase 1: warp 0 computes W[n,h] = sum_e w[dst_e, h]
    if (tid < 32) {
        float4 p0 = make_float4(0.f, 0.f, 0.f, 0.f);
        float4 p1 = make_float4(0.f, 0.f, 0.f, 0.f);
        for (int i = rs + tid; i < re; i += 32) {
            int d = g_col[i];
            const float4* wp = (const float4*)&g_w[(size_t)d * 8];
            float4 w0 = wp[0], w1 = wp[1];
            p0.x += w0.x; p0.y += w0.y; p0.z += w0.z; p0.w += w0.w;
            p1.x += w1.x; p1.y += w1.y; p1.z += w1.z; p1.w += w1.w;
        }
        #pragma unroll
        for (int off = 16; off > 0; off >>= 1) {
            p0.x += __shfl_xor_sync(0xffffffffu, p0.x, off);
            p0.y += __shfl_xor_sync(0xffffffffu, p0.y, off);
            p0.z += __shfl_xor_sync(0xffffffffu, p0.z, off);
            p0.w += __shfl_xor_sync(0xffffffffu, p0.w, off);
            p1.x += __shfl_xor_sync(0xffffffffu, p1.x, off);
            p1.y += __shfl_xor_sync(0xffffffffu, p1.y, off);
            p1.z += __shfl_xor_sync(0xffffffffu, p1.z, off);
            p1.w += __shfl_xor_sync(0xffffffffu, p1.w, off);
        }
        if (tid == 0) {
            s_invW[0] = 1.f / p0.x; s_invW[1] = 1.f / p0.y;
            s_invW[2] = 1.f / p0.z; s_invW[3] = 1.f / p0.w;
            s_invW[4] = 1.f / p1.x; s_invW[5] = 1.f / p1.y;
            s_invW[6] = 1.f / p1.z; s_invW[7] = 1.f / p1.w;
        }
    }
    __syncthreads();

    float invW = s_invW[h];
    float4 acc = make_float4(0.f, 0.f, 0.f, 0.f);
    const uint2* th2 = (const uint2*)g_th;   // 8 bytes = 4 fp16 per thread

    for (int base = rs; base < re; base += 128) {
        int nload = min(128, re - base);
        if (tid < nload) s_col[tid] = g_col[base + tid];
        __syncthreads();
        #pragma unroll 4
        for (int e = 0; e < nload; ++e) {
            int d = s_col[e];
            float coef = __ldg(&g_w[(size_t)d * 8 + h]) * invW;
            uint2 v = th2[(size_t)d * 128 + tid];   // coalesced 1KB row gather
            float2 f0 = __half22float2(*(__half2*)&v.x);
            float2 f1 = __half22float2(*(__half2*)&v.y);
            acc.x = fmaf(coef, f0.x, acc.x);
            acc.y = fmaf(coef, f0.y, acc.y);
            acc.z = fmaf(coef, f1.x, acc.z);
            acc.w = fmaf(coef, f1.y, acc.w);
        }
        __syncthreads();
    }

    float4 r;
    r.x = acc.x > 0.f ? acc.x : expm1f(acc.x);
    r.y = acc.y > 0.f ? acc.y : expm1f(acc.y);
    r.z = acc.z > 0.f ? acc.z : expm1f(acc.z);
    r.w = acc.w > 0.f ? acc.w : expm1f(acc.w);
    __stcs((float4*)&out[(size_t)n * HO + tid * 4], r);  // stream out, keep L2 for t
}

// ---------------- launch ----------------------------------------------------
extern "C" void kernel_launch(void* const* d_in, const int* in_sizes, int n_in,
                              void* d_out, int out_size) {
    const float* x   = (const float*)d_in[0];
    const int*   src = (const int*)  d_in[1];
    const int*   dst = (const int*)  d_in[2];
    const float* Ws  = (const float*)d_in[3];
    const float* As  = (const float*)d_in[4];
    float* out = (float*)d_out;

    int N = in_sizes[0] / IN_F;   // 50000
    int E = in_sizes[1];          // 1600000

    // CSR build (by src)
    k_zero<<<(N + 255) / 256, 256>>>(N);
    k_hist<<<(E + 255) / 256, 256>>>(src, E);
    int B = (N + 1023) / 1024;
    k_scan1<<<B, 1024>>>(N);
    k_scan2<<<1, 1>>>(B);
    k_scan3<<<B, 1024>>>(N);
    k_scatter<<<(E + 255) / 256, 256>>>(src, dst, E);

    // fused: feature transform (fp16 t) + attention logits
    dim3 gg((N + 127) / 128, HO / 128);
    k_gemm<<<gg, 256>>>(x, Ws, As, N);
    k_exps<<<(N * HEADS + 255) / 256, 256>>>(N * HEADS);

    // softmax-weighted aggregation + ELU
    k_agg<<<N, 128>>>(out);
}

// round 8
// speedup vs baseline: 2.0112x; 1.3143x over previous
#include <cuda_runtime.h>
#include <cuda_fp16.h>
#include <math.h>
#include <stdint.h>

// Problem constants (fixed by the dataset)
#define HEADS   8
#define OUT_F   64
#define HO      512          // HEADS * OUT_F
#define IN_F    256
#define MAXN    50048        // padded node count (multiple of 128)
#define MAXE    1600000

// ---------------- scratch (static __device__ globals, no runtime alloc) -----
__device__ __align__(16) static __half g_th[(size_t)MAXN * HO]; // 51.2 MB fp16 t (gather)
__device__ __align__(16) static float  g_w[(size_t)MAXN * HEADS]; // exp(logit)
__device__ static int g_cnt[MAXN];
__device__ static int g_rowptr[MAXN + 1];
__device__ static int g_cur[MAXN];
__device__ static int g_col[MAXE];
__device__ static int g_part[128];

// ---------------- CSR build -------------------------------------------------
__global__ void k_zero(int n) {
    int i = blockIdx.x * blockDim.x + threadIdx.x;
    if (i < n) g_cnt[i] = 0;
}

__global__ void k_hist(const int* __restrict__ src, int E) {
    int i = blockIdx.x * blockDim.x + threadIdx.x;
    if (i < E) atomicAdd(&g_cnt[src[i]], 1);
}

__global__ void k_scan1(int N) {
    __shared__ int s[1024];
    int tid = threadIdx.x;
    int i = blockIdx.x * 1024 + tid;
    int v = (i < N) ? g_cnt[i] : 0;
    s[tid] = v;
    __syncthreads();
    #pragma unroll
    for (int off = 1; off < 1024; off <<= 1) {
        int add = (tid >= off) ? s[tid - off] : 0;
        __syncthreads();
        s[tid] += add;
        __syncthreads();
    }
    if (i < N) g_rowptr[i + 1] = s[tid];
    if (tid == 1023) g_part[blockIdx.x] = s[1023];
}

__global__ void k_scan2(int B) {
    int run = 0;
    for (int b = 0; b < B; ++b) { int t = g_part[b]; g_part[b] = run; run += t; }
}

__global__ void k_scan3(int N) {
    int i = blockIdx.x * 1024 + threadIdx.x;
    if (i < N) {
        int rp = g_rowptr[i + 1] + g_part[blockIdx.x];
        g_rowptr[i + 1] = rp;
        if (i + 1 < N) g_cur[i + 1] = rp;
    }
    if (i == 0) { g_rowptr[0] = 0; g_cur[0] = 0; }
}

__global__ void k_scatter(const int* __restrict__ src, const int* __restrict__ dst, int E) {
    int i = blockIdx.x * blockDim.x + threadIdx.x;
    if (i < E) {
        int p = atomicAdd(&g_cur[src[i]], 1);
        g_col[p] = dst[i];
    }
}

// ---------------- tf32 MMA GEMM (cp.async double-buffered) ------------------
// t = x (M x 256) · Ws^T (256 x 512). BM=BN=128, BK=32, 2-stage pipeline.
// smem row-major [row][k] with pad 36 (36 mod 32 = 4 => fragment loads map
// addr%32 == lane: conflict-free). fp32 fed to tf32 MMA (HW truncates).
// Epilogue: fp16 t store + fused per-row exp(logit) for the block's 2 heads.
#define SMPAD 36
#define ABUF  4608            // 128*36 floats per stage
#define GEMM_SMEM ((2*ABUF*2 + 128 + 256) * 4)   // 75264 B

__device__ __forceinline__ void cp16(void* smem_dst, const void* gsrc, int nbytes) {
    uint32_t s = (uint32_t)__cvta_generic_to_shared(smem_dst);
    asm volatile("cp.async.ca.shared.global [%0], [%1], 16, %2;\n"
                 :: "r"(s), "l"(gsrc), "r"(nbytes));
}

__global__ __launch_bounds__(256) void k_gemm(const float* __restrict__ A,
                                              const float* __restrict__ B,
                                              const float* __restrict__ As_in,
                                              int M) {
    extern __shared__ float dyn[];
    float* pA      = dyn;                 // [2][128][SMPAD]
    float* pB      = dyn + 2 * ABUF;      // [2][128][SMPAD]
    float* s_ar    = dyn + 4 * ABUF;      // [128]
    float* s_logit = s_ar + 128;          // [128][2]

    int tid  = threadIdx.x;
    int lane = tid & 31;
    int warp = tid >> 5;
    int wm   = (warp & 1) * 64;
    int wn   = (warp >> 1) * 32;
    int m0   = blockIdx.x * 128;
    int n0   = blockIdx.y * 128;

    if (tid < 128) {
        int c = n0 + tid;
        s_ar[tid] = As_in[(c >> 6) * 128 + 64 + (c & 63)];
    }
    s_logit[tid] = 0.f;   // 256 floats total, 256 threads

    int lrow = tid >> 3;            // 0..31 step per r: +32? no: id covers below
    (void)lrow;

    float acc[4][4][4];
    #pragma unroll
    for (int mi = 0; mi < 4; ++mi)
        #pragma unroll
        for (int ni = 0; ni < 4; ++ni)
            #pragma unroll
            for (int j = 0; j < 4; ++j) acc[mi][ni][j] = 0.f;

    // stage issue: 128 rows x 32 floats for A and B = 1024 16B chunks each
    #define ISSUE(k0, buf)                                                     \
        do {                                                                   \
            _Pragma("unroll")                                                  \
            for (int r = 0; r < 4; ++r) {                                      \
                int id  = r * 256 + tid;                                       \
                int row = id >> 3;                                             \
                int c4  = (id & 7) * 4;                                        \
                cp16(&pA[(buf) * ABUF + row * SMPAD + c4],                     \
                     &A[(size_t)(m0 + row) * IN_F + (k0) + c4],                \
                     (m0 + row < M) ? 16 : 0);                                 \
                cp16(&pB[(buf) * ABUF + row * SMPAD + c4],                     \
                     &B[(size_t)(n0 + row) * IN_F + (k0) + c4], 16);           \
            }                                                                  \
            asm volatile("cp.async.commit_group;\n");                          \
        } while (0)

    ISSUE(0, 0);

    int lr = lane >> 2;   // 0..7
    int lc = lane & 3;    // 0..3

    for (int k0i = 0; k0i < 8; ++k0i) {
        int cur = k0i & 1;
        if (k0i < 7) {
            ISSUE((k0i + 1) * 32, cur ^ 1);
            asm volatile("cp.async.wait_group 1;\n");
        } else {
            asm volatile("cp.async.wait_group 0;\n");
        }
        __syncthreads();

        const float* Ab = pA + cur * ABUF;
        const float* Bb = pB + cur * ABUF;
        #pragma unroll
        for (int kk = 0; kk < 32; kk += 8) {
            uint32_t afr[4][4];
            uint32_t bfr[4][2];
            #pragma unroll
            for (int mi = 0; mi < 4; ++mi) {
                int rb = wm + mi * 16;
                afr[mi][0] = __float_as_uint(Ab[(rb + lr    ) * SMPAD + kk + lc    ]);
                afr[mi][1] = __float_as_uint(Ab[(rb + lr + 8) * SMPAD + kk + lc    ]);
                afr[mi][2] = __float_as_uint(Ab[(rb + lr    ) * SMPAD + kk + lc + 4]);
                afr[mi][3] = __float_as_uint(Ab[(rb + lr + 8) * SMPAD + kk + lc + 4]);
            }
            #pragma unroll
            for (int ni = 0; ni < 4; ++ni) {
                int nb = wn + ni * 8;
                bfr[ni][0] = __float_as_uint(Bb[(nb + lr) * SMPAD + kk + lc    ]);
                bfr[ni][1] = __float_as_uint(Bb[(nb + lr) * SMPAD + kk + lc + 4]);
            }
            #pragma unroll
            for (int mi = 0; mi < 4; ++mi)
                #pragma unroll
                for (int ni = 0; ni < 4; ++ni) {
                    asm volatile(
                        "mma.sync.aligned.m16n8k8.row.col.f32.tf32.tf32.f32 "
                        "{%0,%1,%2,%3}, {%4,%5,%6,%7}, {%8,%9}, {%0,%1,%2,%3};\n"
                        : "+f"(acc[mi][ni][0]), "+f"(acc[mi][ni][1]),
                          "+f"(acc[mi][ni][2]), "+f"(acc[mi][ni][3])
                        : "r"(afr[mi][0]), "r"(afr[mi][1]),
                          "r"(afr[mi][2]), "r"(afr[mi][3]),
                          "r"(bfr[ni][0]), "r"(bfr[ni][1]));
                }
        }
        __syncthreads();
    }

    // epilogue: fp16 t store + block-local logit reduction
    int head_local = warp >> 2;   // warps 0-3 -> head 0 of block; 4-7 -> head 1
    #pragma unroll
    for (int mi = 0; mi < 4; ++mi) {
        int r0 = m0 + wm + mi * 16 + lr;
        int r1 = r0 + 8;
        float p0 = 0.f, p1 = 0.f;
        #pragma unroll
        for (int ni = 0; ni < 4; ++ni) {
            int cl = wn + ni * 8 + lc * 2;    // block-local col
            int c  = n0 + cl;
            p0 = fmaf(acc[mi][ni][0], s_ar[cl], fmaf(acc[mi][ni][1], s_ar[cl + 1], p0));
            p1 = fmaf(acc[mi][ni][2], s_ar[cl], fmaf(acc[mi][ni][3], s_ar[cl + 1], p1));
            if (r0 < M)
                *(__half2*)&g_th[(size_t)r0 * HO + c] =
                    __floats2half2_rn(acc[mi][ni][0], acc[mi][ni][1]);
            if (r1 < M)
                *(__half2*)&g_th[(size_t)r1 * HO + c] =
                    __floats2half2_rn(acc[mi][ni][2], acc[mi][ni][3]);
        }
        atomicAdd(&s_logit[(wm + mi * 16 + lr    ) * 2 + head_local], p0);
        atomicAdd(&s_logit[(wm + mi * 16 + lr + 8) * 2 + head_local], p1);
    }
    __syncthreads();

    if (tid < 128 && m0 + tid < M) {
        int hb = blockIdx.y * 2;
        g_w[(size_t)(m0 + tid) * HEADS + hb    ] = expf(s_logit[tid * 2 + 0]);
        g_w[(size_t)(m0 + tid) * HEADS + hb + 1] = expf(s_logit[tid * 2 + 1]);
    }
}

// ---------------- aggregation + ELU (fp16 gather, post-normalize) -----------
// One block (128 thr) per node. Thread j owns out[n, 4j..4j+3]; head h = j/16.
// h[n] = (sum_e w_d * t_d) / (sum_e w_d): softmax normalization moved to the
// end (Al and the max-shift cancel; the denominator is just sum of the same
// per-edge weights already loaded in the loop).
__global__ __launch_bounds__(128) void k_agg(float* __restrict__ out) {
    __shared__ int s_col[128];

    int n   = blockIdx.x;
    int tid = threadIdx.x;
    int rs  = g_rowptr[n];
    int re  = g_rowptr[n + 1];
    int h   = tid >> 4;

    if (re == rs) {  // no outgoing edges: out = elu(0) = 0
        *(float4*)&out[(size_t)n * HO + tid * 4] = make_float4(0.f, 0.f, 0.f, 0.f);
        return;
    }

    float  ws  = 0.f;
    float4 acc = make_float4(0.f, 0.f, 0.f, 0.f);
    const uint2* th2 = (const uint2*)g_th;   // 8 bytes = 4 fp16 per thread

    for (int base = rs; base < re; base += 128) {
        int nload = min(128, re - base);
        __syncthreads();
        if (tid < nload) s_col[tid] = g_col[base + tid];
        __syncthreads();
        #pragma unroll 4
        for (int e = 0; e < nload; ++e) {
            int d = s_col[e];
            float wv = __ldg(&g_w[(size_t)d * 8 + h]);
            ws += wv;
            uint2 v = th2[(size_t)d * 128 + tid];   // coalesced 1KB row gather
            float2 f0 = __half22float2(*(__half2*)&v.x);
            float2 f1 = __half22float2(*(__half2*)&v.y);
            acc.x = fmaf(wv, f0.x, acc.x);
            acc.y = fmaf(wv, f0.y, acc.y);
            acc.z = fmaf(wv, f1.x, acc.z);
            acc.w = fmaf(wv, f1.y, acc.w);
        }
    }

    float inv = 1.f / ws;
    acc.x *= inv; acc.y *= inv; acc.z *= inv; acc.w *= inv;

    float4 r;
    r.x = acc.x > 0.f ? acc.x : expm1f(acc.x);
    r.y = acc.y > 0.f ? acc.y : expm1f(acc.y);
    r.z = acc.z > 0.f ? acc.z : expm1f(acc.z);
    r.w = acc.w > 0.f ? acc.w : expm1f(acc.w);
    __stcs((float4*)&out[(size_t)n * HO + tid * 4], r);  // stream out, keep t in L2
}

// ---------------- launch ----------------------------------------------------
extern "C" void kernel_launch(void* const* d_in, const int* in_sizes, int n_in,
                              void* d_out, int out_size) {
    const float* x   = (const float*)d_in[0];
    const int*   src = (const int*)  d_in[1];
    const int*   dst = (const int*)  d_in[2];
    const float* Ws  = (const float*)d_in[3];
    const float* As  = (const float*)d_in[4];
    float* out = (float*)d_out;

    int N = in_sizes[0] / IN_F;   // 50000
    int E = in_sizes[1];          // 1600000

    // CSR build (by src)
    k_zero<<<(N + 255) / 256, 256>>>(N);
    k_hist<<<(E + 255) / 256, 256>>>(src, E);
    int B = (N + 1023) / 1024;
    k_scan1<<<B, 1024>>>(N);
    k_scan2<<<1, 1>>>(B);
    k_scan3<<<B, 1024>>>(N);
    k_scatter<<<(E + 255) / 256, 256>>>(src, dst, E);

    // fused: feature transform (fp16 t) + attention weights exp(logit)
    cudaFuncSetAttribute(k_gemm, cudaFuncAttributeMaxDynamicSharedMemorySize,
                         GEMM_SMEM);
    dim3 gg((N + 127) / 128, HO / 128);
    k_gemm<<<gg, 256, GEMM_SMEM>>>(x, Ws, As, N);

    // softmax-weighted aggregation + ELU
    k_agg<<<N, 128>>>(out);
}